// round 11
// baseline (speedup 1.0000x reference)
#include <cuda_runtime.h>
#include <cuda_bf16.h>
#include <math.h>

// ---------------- problem constants ----------------
#define B_ 256
#define T_ 36
#define S_ 96
#define D_ 1024
#define H_ 1024
#define L_ 2

static const long Y_SZ   = (long)B_*T_*D_;
static const long HID_SZ = (long)L_*B_*H_;

// ---------------- bf16 weight buffers (hi/lo split) -------------------------
#define NW_ATTN (96L*2048L)
#define NW_COMB (1024L*2048L)
#define NW_IH   (2L*3072L*1024L)
#define NW_HH   (2L*3072L*1024L)
#define NW_O1   (1024L*1024L)
#define NW_O2   (1024L*1024L)
#define OW_ATTN 0L
#define OW_COMB (OW_ATTN + NW_ATTN)
#define OW_IH   (OW_COMB + NW_COMB)
#define OW_HH   (OW_IH   + NW_IH)
#define OW_O1   (OW_HH   + NW_HH)
#define OW_O2   (OW_O1   + NW_O1)
#define TOTW    (OW_O2   + NW_O2)

__device__ __nv_bfloat16 g_whi[TOTW];
__device__ __nv_bfloat16 g_wlo[TOTW];

// ---------------- bf16 activation buffers (hi/lo split) ---------------------
#define OB_X   0L
#define OB_H   (OB_X  + (long)B_*T_*D_)      // h0 at OB_H, h1 at OB_H + B*H
#define OB_XC  (OB_H  + 2L*B_*H_)
#define OB_T1  (OB_XC + (long)B_*D_)
#define OB_WE  (OB_T1 + (long)B_*D_)
#define TOTB   (OB_WE + (long)B_*H_)

__device__ __nv_bfloat16 g_bhi[TOTB];
__device__ __nv_bfloat16 g_blo[TOTB];

// ---------------- fp32 split-K partial buffers ------------------------------
#define OP_ATTN 0L                            // 8 slices of B*S
#define OP_COMB (OP_ATTN + 8L*B_*S_)          // 4 slices of B*D
#define OP_GI0  (OP_COMB + 4L*B_*D_)          // 2 slices of B*3H
#define OP_GH0  (OP_GI0  + 2L*B_*3*H_)
#define OP_GI1  (OP_GH0  + 2L*B_*3*H_)
#define OP_GH1  (OP_GI1  + 2L*B_*3*H_)
#define OP_T1   (OP_GH1  + 2L*B_*3*H_)        // 4 slices of B*D
#define OP_Y    (OP_T1   + 4L*B_*D_)          // 4 slices of B*D
#define TOTP    (OP_Y    + 4L*B_*D_)

__device__ float g_part[TOTP];

// ---------------- split helpers ----------------
__device__ __forceinline__ void split2(float a, float b, unsigned& h, unsigned& l) {
    __nv_bfloat16 ha = __float2bfloat16(a), hb = __float2bfloat16(b);
    __nv_bfloat16 la = __float2bfloat16(a - __bfloat162float(ha));
    __nv_bfloat16 lb = __float2bfloat16(b - __bfloat162float(hb));
    h = ((unsigned)__bfloat16_as_ushort(hb) << 16) | (unsigned)__bfloat16_as_ushort(ha);
    l = ((unsigned)__bfloat16_as_ushort(lb) << 16) | (unsigned)__bfloat16_as_ushort(la);
}

__device__ __forceinline__ void split_store4(float4 a, __nv_bfloat16* hi,
                                             __nv_bfloat16* lo, long idx) {
    unsigned h01, h23, l01, l23;
    split2(a.x, a.y, h01, l01);
    split2(a.z, a.w, h23, l23);
    *reinterpret_cast<uint2*>(hi + idx) = make_uint2(h01, h23);
    *reinterpret_cast<uint2*>(lo + idx) = make_uint2(l01, l23);
}

// ---------------- weight/activation split conversion ------------------------
__global__ void wconv(const float* __restrict__ s, __nv_bfloat16* __restrict__ hi,
                      __nv_bfloat16* __restrict__ lo, int n) {
    int i = blockIdx.x * 256 + threadIdx.x;
    if (i >= n) return;
    float v = s[i];
    __nv_bfloat16 h = __float2bfloat16(v);
    hi[i] = h;
    lo[i] = __float2bfloat16(v - __bfloat162float(h));
}

// ---------------- mma wrapper ----------------
__device__ __forceinline__ void mma16816(float* c, const unsigned* a, const unsigned* b) {
    asm volatile(
        "mma.sync.aligned.m16n8k16.row.col.f32.bf16.bf16.f32 "
        "{%0,%1,%2,%3}, {%4,%5,%6,%7}, {%8,%9}, {%0,%1,%2,%3};\n"
        : "+f"(c[0]), "+f"(c[1]), "+f"(c[2]), "+f"(c[3])
        : "r"(a[0]), "r"(a[1]), "r"(a[2]), "r"(a[3]), "r"(b[0]), "r"(b[1]));
}

// ---------------- dual-problem split-K pure-bf16 tensor GEMM ----------------
// C_part[zl][m][n] = sum_{k in slice} (Ahi+Alo)[m,k] * (Whi+Wlo)[n,k]
// via 3 products hi*hi + hi*lo + lo*hi, fp32 accum. A = virtual concat
// (k<K1 -> A1 else A2), all operands pre-split bf16. Store epilogue (no atomics).
struct GemmSet {
    const __nv_bfloat16 *A1h, *A1l, *A2h, *A2l;
    const __nv_bfloat16 *Wh, *Wl;
    float* C;
    int K1, lda1, lda2, ldw, ldc, N, K, Kslice, zcount;
};

__global__ __launch_bounds__(128) void hgemm_dual(GemmSet s0, GemmSet s1) {
    const int zg = blockIdx.z;
    const GemmSet& g = (zg < s0.zcount) ? s0 : s1;
    const int zl = (zg < s0.zcount) ? zg : zg - s0.zcount;
    const int n0 = blockIdx.x * 64, m0 = blockIdx.y * 64;
    if (n0 >= g.N) return;

    // [buf][row][20 u32] : 40 bf16 stride -> conflict-benign fragment loads
    __shared__ unsigned sAh[2][64][20], sAl[2][64][20], sWh[2][64][20], sWl[2][64][20];

    const int tid = threadIdx.x;
    const int warp = tid >> 5, lane = tid & 31;
    const int gq = lane >> 2, tq = lane & 3;
    const int wm0 = (warp & 1) * 32, wn0 = (warp >> 1) * 32;
    const int r = tid >> 1, half = tid & 1;

    const int kstart = zl * g.Kslice;
    const int kend = min(g.K, kstart + g.Kslice);
    const int nch = (kend - kstart) >> 5;   // KC = 32

    float acc[2][4][4];
#pragma unroll
    for (int mt = 0; mt < 2; mt++)
#pragma unroll
        for (int nt = 0; nt < 4; nt++)
#pragma unroll
            for (int q = 0; q < 4; q++) acc[mt][nt][q] = 0.f;

    float4 pa[4], pw[4];

    auto fetch = [&](int c) {
        int k = kstart + 32 * c + half * 16;
        const __nv_bfloat16 *ph, *pl;
        if (k < g.K1) {
            long o = (long)(m0 + r) * g.lda1 + k;
            ph = g.A1h + o; pl = g.A1l + o;
        } else {
            long o = (long)(m0 + r) * g.lda2 + (k - g.K1);
            ph = g.A2h + o; pl = g.A2l + o;
        }
        pa[0] = *reinterpret_cast<const float4*>(ph);
        pa[1] = *reinterpret_cast<const float4*>(ph + 8);
        pa[2] = *reinterpret_cast<const float4*>(pl);
        pa[3] = *reinterpret_cast<const float4*>(pl + 8);
        int n = n0 + r;
        if (n < g.N) {
            const __nv_bfloat16* wh = g.Wh + (long)n * g.ldw + k;
            const __nv_bfloat16* wl = g.Wl + (long)n * g.ldw + k;
            pw[0] = *reinterpret_cast<const float4*>(wh);
            pw[1] = *reinterpret_cast<const float4*>(wh + 8);
            pw[2] = *reinterpret_cast<const float4*>(wl);
            pw[3] = *reinterpret_cast<const float4*>(wl + 8);
        } else {
            float4 z = make_float4(0.f, 0.f, 0.f, 0.f);
            pw[0] = z; pw[1] = z; pw[2] = z; pw[3] = z;
        }
    };
    auto stage = [&](int bs) {
        float4* d;
        d = reinterpret_cast<float4*>((char*)&sAh[bs][r][0] + half * 32); d[0] = pa[0]; d[1] = pa[1];
        d = reinterpret_cast<float4*>((char*)&sAl[bs][r][0] + half * 32); d[0] = pa[2]; d[1] = pa[3];
        d = reinterpret_cast<float4*>((char*)&sWh[bs][r][0] + half * 32); d[0] = pw[0]; d[1] = pw[1];
        d = reinterpret_cast<float4*>((char*)&sWl[bs][r][0] + half * 32); d[0] = pw[2]; d[1] = pw[3];
    };

    fetch(0);
    stage(0);
    __syncthreads();

    for (int c = 0; c < nch; c++) {
        if (c + 1 < nch) fetch(c + 1);

        const int cb = c & 1;
        const unsigned* pAh = &sAh[cb][0][0];
        const unsigned* pAl = &sAl[cb][0][0];
        const unsigned* pWh = &sWh[cb][0][0];
        const unsigned* pWl = &sWl[cb][0][0];
#pragma unroll
        for (int kk = 0; kk < 2; kk++) {
            const int kw = kk * 8;
            unsigned ah[2][4], al[2][4], bh[4][2], bl[4][2];
#pragma unroll
            for (int mt = 0; mt < 2; mt++) {
                int base = (wm0 + mt * 16 + gq) * 20 + kw + tq;
                ah[mt][0] = pAh[base];       ah[mt][1] = pAh[base + 160];
                ah[mt][2] = pAh[base + 4];   ah[mt][3] = pAh[base + 164];
                al[mt][0] = pAl[base];       al[mt][1] = pAl[base + 160];
                al[mt][2] = pAl[base + 4];   al[mt][3] = pAl[base + 164];
            }
#pragma unroll
            for (int nt = 0; nt < 4; nt++) {
                int base = (wn0 + nt * 8 + gq) * 20 + kw + tq;
                bh[nt][0] = pWh[base]; bh[nt][1] = pWh[base + 4];
                bl[nt][0] = pWl[base]; bl[nt][1] = pWl[base + 4];
            }
#pragma unroll
            for (int mt = 0; mt < 2; mt++)
#pragma unroll
                for (int nt = 0; nt < 4; nt++) {
                    mma16816(acc[mt][nt], ah[mt], bh[nt]);
                    mma16816(acc[mt][nt], ah[mt], bl[nt]);
                    mma16816(acc[mt][nt], al[mt], bh[nt]);
                }
        }
        if (c + 1 < nch) stage((c + 1) & 1);
        __syncthreads();
    }

    // ---- store epilogue into this z-slice's partial buffer ----
    float* Cs = g.C + (long)zl * ((long)256 * g.ldc);
#pragma unroll
    for (int mt = 0; mt < 2; mt++) {
        int m = m0 + wm0 + mt * 16 + gq;
#pragma unroll
        for (int nt = 0; nt < 4; nt++) {
            int n = n0 + wn0 + nt * 8 + 2 * tq;
            if (n < g.N) {
                *reinterpret_cast<float2*>(Cs + (long)m * g.ldc + n) =
                    make_float2(acc[mt][nt][0], acc[mt][nt][1]);
                *reinterpret_cast<float2*>(Cs + (long)(m + 8) * g.ldc + n) =
                    make_float2(acc[mt][nt][2], acc[mt][nt][3]);
            }
        }
    }
}

// ---------------- fused logits-reduce + softmax + weighted enc --------------
// grid (8, B), 32 threads. Reduces 8 logit slices, softmax, writes outAttn
// (chunk 0), then accumulates a 128-wide H chunk of w_enc and stores it split.
__global__ void softmax_wenc(const float* __restrict__ lp,
                             const float* __restrict__ bias,
                             float* __restrict__ outAttn, int t,
                             const float* __restrict__ enc,
                             __nv_bfloat16* __restrict__ whi,
                             __nv_bfloat16* __restrict__ wlo) {
    __shared__ float sw[S_];
    const int b = blockIdx.y, c = blockIdx.x, lane = threadIdx.x;
    float v[3];
#pragma unroll
    for (int j = 0; j < 3; j++) {
        int s = lane + 32 * j;
        float a = bias[s];
#pragma unroll
        for (int z = 0; z < 8; z++) a += lp[(long)z * (B_ * S_) + b * S_ + s];
        v[j] = a;
    }
    float mx = fmaxf(v[0], fmaxf(v[1], v[2]));
#pragma unroll
    for (int o = 16; o; o >>= 1) mx = fmaxf(mx, __shfl_xor_sync(0xffffffffu, mx, o));
    float e[3], sum = 0.f;
#pragma unroll
    for (int j = 0; j < 3; j++) { e[j] = expf(v[j] - mx); sum += e[j]; }
#pragma unroll
    for (int o = 16; o; o >>= 1) sum += __shfl_xor_sync(0xffffffffu, sum, o);
    const float inv = 1.f / sum;
#pragma unroll
    for (int j = 0; j < 3; j++) sw[lane + 32 * j] = e[j] * inv;
    __syncwarp();
    if (c == 0) {
#pragma unroll
        for (int j = 0; j < 3; j++)
            outAttn[((long)b * T_ + t) * S_ + lane + 32 * j] = sw[lane + 32 * j];
    }
    const float4* ep = reinterpret_cast<const float4*>(enc + (long)b * S_ * H_) + c * 32 + lane;
    float4 acc = make_float4(0.f, 0.f, 0.f, 0.f);
#pragma unroll 4
    for (int s = 0; s < S_; s++) {
        float w = sw[s];
        float4 x = ep[(long)s * (H_ / 4)];
        acc.x = fmaf(w, x.x, acc.x);
        acc.y = fmaf(w, x.y, acc.y);
        acc.z = fmaf(w, x.z, acc.z);
        acc.w = fmaf(w, x.w, acc.w);
    }
    split_store4(acc, whi, wlo, (long)b * H_ + c * 128 + lane * 4);
}

// ---------------- reduce 4 split-K partials + bias (+relu) + bf16-split -----
__global__ void reduce_split(const float* __restrict__ P,
                             const float* __restrict__ bias, int relu,
                             __nv_bfloat16* __restrict__ hi,
                             __nv_bfloat16* __restrict__ lo) {
    int i4 = blockIdx.x * 256 + threadIdx.x;            // over B*D/4
    int d4 = i4 & (D_ / 4 - 1);
    float4 a = reinterpret_cast<const float4*>(bias)[d4];
#pragma unroll
    for (int z = 0; z < 4; z++) {
        float4 p = reinterpret_cast<const float4*>(P)[(long)z * (B_ * D_ / 4) + i4];
        a.x += p.x; a.y += p.y; a.z += p.z; a.w += p.w;
    }
    if (relu) {
        a.x = fmaxf(a.x, 0.f); a.y = fmaxf(a.y, 0.f);
        a.z = fmaxf(a.z, 0.f); a.w = fmaxf(a.w, 0.f);
    }
    split_store4(a, hi, lo, (long)i4 * 4);
}

// ---------------- GRU gate: reduce 2+2 partials, h = (1-z)*n + z*h ----------
__global__ void gru_gate(const float* __restrict__ giP, const float* __restrict__ ghP,
                         const float* __restrict__ bi, const float* __restrict__ bh,
                         float* __restrict__ h,
                         __nv_bfloat16* __restrict__ hhi,
                         __nv_bfloat16* __restrict__ hlo) {
    int i4 = blockIdx.x * 256 + threadIdx.x;            // over B*H/4
    int b = i4 >> 8, j4 = i4 & 255;
    const long row4 = (long)b * (3 * H_ / 4);
    const long ss4 = (long)B_ * 3 * H_ / 4;
    const float4* bi4 = reinterpret_cast<const float4*>(bi);
    const float4* bh4 = reinterpret_cast<const float4*>(bh);
    const float4* gi4 = reinterpret_cast<const float4*>(giP);
    const float4* gh4 = reinterpret_cast<const float4*>(ghP);

    float4 ir = bi4[j4], iz = bi4[j4 + 256], in_ = bi4[j4 + 512];
    float4 hr = bh4[j4], hz = bh4[j4 + 256], hn = bh4[j4 + 512];
#pragma unroll
    for (int z = 0; z < 2; z++) {
        long o = z * ss4 + row4;
        float4 p;
        p = gi4[o + j4];       ir.x += p.x; ir.y += p.y; ir.z += p.z; ir.w += p.w;
        p = gi4[o + j4 + 256]; iz.x += p.x; iz.y += p.y; iz.z += p.z; iz.w += p.w;
        p = gi4[o + j4 + 512]; in_.x += p.x; in_.y += p.y; in_.z += p.z; in_.w += p.w;
        p = gh4[o + j4];       hr.x += p.x; hr.y += p.y; hr.z += p.z; hr.w += p.w;
        p = gh4[o + j4 + 256]; hz.x += p.x; hz.y += p.y; hz.z += p.z; hz.w += p.w;
        p = gh4[o + j4 + 512]; hn.x += p.x; hn.y += p.y; hn.z += p.z; hn.w += p.w;
    }
    float4 hv = reinterpret_cast<float4*>(h)[i4];
    float rr[4] = {ir.x + hr.x, ir.y + hr.y, ir.z + hr.z, ir.w + hr.w};
    float zz[4] = {iz.x + hz.x, iz.y + hz.y, iz.z + hz.z, iz.w + hz.w};
    float nn[4] = {in_.x, in_.y, in_.z, in_.w};
    float hnv[4] = {hn.x, hn.y, hn.z, hn.w};
    float ho[4] = {hv.x, hv.y, hv.z, hv.w};
    float res[4];
#pragma unroll
    for (int q = 0; q < 4; q++) {
        float r = 1.f / (1.f + expf(-rr[q]));
        float z = 1.f / (1.f + expf(-zz[q]));
        float n = tanhf(nn[q] + r * hnv[q]);
        res[q] = (1.f - z) * n + z * ho[q];
    }
    float4 out = make_float4(res[0], res[1], res[2], res[3]);
    reinterpret_cast<float4*>(h)[i4] = out;
    split_store4(out, hhi, hlo, (long)i4 * 4);
}

// ---------------- y writeback: reduce 4 partials + out2 bias ----------------
__global__ void copy_y(const float* __restrict__ P, const float* __restrict__ b2,
                       float* __restrict__ outy, int t) {
    int i4 = blockIdx.x * 256 + threadIdx.x;            // over B*D/4
    int b = i4 >> 8, d4 = i4 & 255;
    float4 a = reinterpret_cast<const float4*>(b2)[d4];
#pragma unroll
    for (int z = 0; z < 4; z++) {
        float4 p = reinterpret_cast<const float4*>(P)[(long)z * (B_ * D_ / 4) + i4];
        a.x += p.x; a.y += p.y; a.z += p.z; a.w += p.w;
    }
    reinterpret_cast<float4*>(outy)[((long)b * T_ + t) * (D_ / 4) + d4] = a;
}

// ---------------- host driver ----------------
static inline GemmSet mkset(const __nv_bfloat16* A1h, const __nv_bfloat16* A1l,
                            const __nv_bfloat16* A2h, const __nv_bfloat16* A2l,
                            int K1, int lda1, int lda2,
                            const __nv_bfloat16* Wh, const __nv_bfloat16* Wl, int ldw,
                            float* C, int ldc, int N, int K, int Kslice, int zc) {
    GemmSet s;
    s.A1h = A1h; s.A1l = A1l; s.A2h = A2h; s.A2l = A2l;
    s.Wh = Wh; s.Wl = Wl; s.C = C;
    s.K1 = K1; s.lda1 = lda1; s.lda2 = lda2; s.ldw = ldw; s.ldc = ldc;
    s.N = N; s.K = K; s.Kslice = Kslice; s.zcount = zc;
    return s;
}

extern "C" void kernel_launch(void* const* d_in, const int* in_sizes, int n_in,
                              void* d_out, int out_size) {
    const float* target = (const float*)d_in[0];   // (B,T,D)
    const float* hidden0= (const float*)d_in[1];   // (L,B,H)
    const float* enc    = (const float*)d_in[2];   // (B,S,H)
    const float* attn_W = (const float*)d_in[3];
    const float* attn_b = (const float*)d_in[4];
    const float* comb_W = (const float*)d_in[5];
    const float* comb_b = (const float*)d_in[6];
    const float* W_ih   = (const float*)d_in[7];
    const float* W_hh   = (const float*)d_in[8];
    const float* b_ih   = (const float*)d_in[9];
    const float* b_hh   = (const float*)d_in[10];
    const float* out1_W = (const float*)d_in[11];
    const float* out1_b = (const float*)d_in[12];
    const float* out2_W = (const float*)d_in[13];
    const float* out2_b = (const float*)d_in[14];

    float* out     = (float*)d_out;
    float* outY    = out;
    float* hid     = out + Y_SZ;
    float* outAttn = out + Y_SZ + HID_SZ;

    __nv_bfloat16 *whi = nullptr, *wlo = nullptr, *bhi = nullptr, *blo = nullptr;
    float* part = nullptr;
    cudaGetSymbolAddress((void**)&whi, g_whi);
    cudaGetSymbolAddress((void**)&wlo, g_wlo);
    cudaGetSymbolAddress((void**)&bhi, g_bhi);
    cudaGetSymbolAddress((void**)&blo, g_blo);
    cudaGetSymbolAddress((void**)&part, g_part);

    float* h0 = hid;
    float* h1 = hid + (long)B_ * H_;
    __nv_bfloat16 *h0hi = bhi + OB_H, *h0lo = blo + OB_H;
    __nv_bfloat16 *h1hi = bhi + OB_H + (long)B_ * H_, *h1lo = blo + OB_H + (long)B_ * H_;

    // ---- per-replay weight + target splits ----
    {
        struct { const float* s; long off; long n; } cv[6] = {
            {attn_W, OW_ATTN, NW_ATTN}, {comb_W, OW_COMB, NW_COMB},
            {W_ih,   OW_IH,   NW_IH},   {W_hh,   OW_HH,   NW_HH},
            {out1_W, OW_O1,   NW_O1},   {out2_W, OW_O2,   NW_O2}};
        for (int i = 0; i < 6; i++)
            wconv<<<(int)((cv[i].n + 255) / 256), 256>>>(cv[i].s, whi + cv[i].off,
                                                         wlo + cv[i].off, (int)cv[i].n);
    }
    wconv<<<(int)(((long)B_*T_*D_ + 255) / 256), 256>>>(target, bhi + OB_X, blo + OB_X,
                                                        (int)((long)B_*T_*D_));
    cudaMemcpyAsync(hid, hidden0, HID_SZ * sizeof(float), cudaMemcpyDeviceToDevice, 0);
    wconv<<<(int)((2L*B_*H_ + 255) / 256), 256>>>(hid, bhi + OB_H, blo + OB_H,
                                                  (int)(2L*B_*H_));

    auto xh = [&](int t) { return bhi + OB_X + (long)t * D_; };
    auto xl = [&](int t) { return blo + OB_X + (long)t * D_; };

    auto set_attn = [&](int t) {
        return mkset(xh(t), xl(t), h1hi, h1lo, D_, T_ * D_, H_,
                     whi + OW_ATTN, wlo + OW_ATTN, D_ + H_,
                     part + OP_ATTN, S_, S_, D_ + H_, 256, 8);
    };
    auto set_comb = [&](int t) {
        return mkset(xh(t), xl(t), bhi + OB_WE, blo + OB_WE, D_, T_ * D_, H_,
                     whi + OW_COMB, wlo + OW_COMB, D_ + H_,
                     part + OP_COMB, D_, D_, D_ + H_, 512, 4);
    };
    auto set_gi0 = [&]() {
        return mkset(bhi + OB_XC, blo + OB_XC, bhi + OB_XC, blo + OB_XC, D_, D_, D_,
                     whi + OW_IH, wlo + OW_IH, D_,
                     part + OP_GI0, 3 * H_, 3 * H_, D_, 512, 2);
    };
    auto set_gh0 = [&]() {
        return mkset(h0hi, h0lo, h0hi, h0lo, H_, H_, H_,
                     whi + OW_HH, wlo + OW_HH, H_,
                     part + OP_GH0, 3 * H_, 3 * H_, H_, 512, 2);
    };
    auto set_gi1 = [&]() {
        return mkset(h0hi, h0lo, h0hi, h0lo, H_, H_, H_,
                     whi + OW_IH + 3L * H_ * D_, wlo + OW_IH + 3L * H_ * D_, D_,
                     part + OP_GI1, 3 * H_, 3 * H_, D_, 512, 2);
    };
    auto set_gh1 = [&]() {
        return mkset(h1hi, h1lo, h1hi, h1lo, H_, H_, H_,
                     whi + OW_HH + 3L * H_ * H_, wlo + OW_HH + 3L * H_ * H_, H_,
                     part + OP_GH1, 3 * H_, 3 * H_, H_, 512, 2);
    };
    auto set_out1 = [&]() {
        return mkset(h1hi, h1lo, h1hi, h1lo, H_, H_, H_,
                     whi + OW_O1, wlo + OW_O1, H_,
                     part + OP_T1, D_, D_, H_, 256, 4);
    };
    auto set_out2 = [&]() {
        return mkset(bhi + OB_T1, blo + OB_T1, bhi + OB_T1, blo + OB_T1, D_, D_, D_,
                     whi + OW_O2, wlo + OW_O2, D_,
                     part + OP_Y, D_, D_, D_, 256, 4);
    };

    auto launch1 = [&](const GemmSet& s) {
        dim3 g((s.N + 63) / 64, B_ / 64, s.zcount);
        GemmSet dummy = s; dummy.zcount = 0;
        hgemm_dual<<<g, 128>>>(s, dummy);
    };
    auto launch2 = [&](const GemmSet& a, const GemmSet& b) {
        int nx = max((a.N + 63) / 64, (b.N + 63) / 64);
        dim3 g(nx, B_ / 64, a.zcount + b.zcount);
        hgemm_dual<<<g, 128>>>(a, b);
    };
    auto do_swenc = [&](int t) {
        softmax_wenc<<<dim3(8, B_), 32>>>(part + OP_ATTN, attn_b, outAttn, t, enc,
                                          bhi + OB_WE, blo + OB_WE);
    };
    auto do_xcpass = [&]() {
        reduce_split<<<256, 256>>>(part + OP_COMB, comb_b, 1, bhi + OB_XC, blo + OB_XC);
    };
    auto do_t1pass = [&]() {
        reduce_split<<<256, 256>>>(part + OP_T1, out1_b, 0, bhi + OB_T1, blo + OB_T1);
    };
    auto do_gru = [&]() {
        launch2(set_gi0(), set_gh0());
        gru_gate<<<256, 256>>>(part + OP_GI0, part + OP_GH0, b_ih, b_hh, h0, h0hi, h0lo);
        launch2(set_gi1(), set_gh1());
        gru_gate<<<256, 256>>>(part + OP_GI1, part + OP_GH1, b_ih + 3 * H_, b_hh + 3 * H_,
                               h1, h1hi, h1lo);
    };

    // ---- software-pipelined schedule ----
    launch1(set_attn(0));
    do_swenc(0);
    launch1(set_comb(0));
    do_xcpass();
    do_gru();

    for (int t = 0; t < T_ - 1; t++) {
        launch2(set_out1(), set_attn(t + 1));   // both read h1 (post step t)
        do_swenc(t + 1);
        do_t1pass();
        launch2(set_out2(), set_comb(t + 1));
        copy_y<<<256, 256>>>(part + OP_Y, out2_b, outY, t);
        do_xcpass();
        do_gru();
    }

    launch1(set_out1());
    do_t1pass();
    launch1(set_out2());
    copy_y<<<256, 256>>>(part + OP_Y, out2_b, outY, T_ - 1);
}

// round 17
// speedup vs baseline: 1.3109x; 1.3109x over previous
#include <cuda_runtime.h>
#include <cuda_bf16.h>
#include <math.h>
#include <stdint.h>

// ---------------- problem constants ----------------
#define B_ 256
#define T_ 36
#define S_ 96
#define D_ 1024
#define H_ 1024

static const long Y_SZ   = (long)B_*T_*D_;          // 9,437,184
static const long HID_SZ = 2L*B_*H_;

// ---------------- bf16 weight buffers (hi/lo split) -------------------------
#define NW_ATTN (96L*2048L)
#define NW_COMB (1024L*2048L)
#define NW_IH   (2L*3072L*1024L)
#define NW_HH   (2L*3072L*1024L)
#define NW_O1   (1024L*1024L)
#define NW_O2   (1024L*1024L)
#define OW_ATTN 0L
#define OW_COMB (OW_ATTN + NW_ATTN)
#define OW_IH   (OW_COMB + NW_COMB)
#define OW_HH   (OW_IH   + NW_IH)
#define OW_O1   (OW_HH   + NW_HH)
#define OW_O2   (OW_O1   + NW_O1)
#define TOTW    (OW_O2   + NW_O2)

__device__ __nv_bfloat16 g_whi[TOTW];
__device__ __nv_bfloat16 g_wlo[TOTW];

// ---------------- bf16 activation buffers (hi/lo split) ---------------------
#define OB_X   0L
#define OB_H   (OB_X  + (long)B_*T_*D_)      // h0 at OB_H, h1 at OB_H + B*H
#define OB_XC  (OB_H  + 2L*B_*H_)
#define OB_WE  (OB_XC + (long)B_*D_)
#define TOTB   (OB_WE + (long)B_*H_)

__device__ __nv_bfloat16 g_bhi[TOTB];
__device__ __nv_bfloat16 g_blo[TOTB];

// ---------------- h1 history (for deferred out-head) + tail buffers ---------
#define NBT ((long)B_*T_*H_)                  // 9,437,184
__device__ __nv_bfloat16 g_histh[NBT];
__device__ __nv_bfloat16 g_histl[NBT];
__device__ __nv_bfloat16 g_t1h[NBT];
__device__ __nv_bfloat16 g_t1l[NBT];
__device__ float g_big[NBT];                  // t1all, then yall (reused)

// ---------------- fp32 split-K partial buffers ------------------------------
#define OP_ATTN 0L                            // 8 slices of B*S
#define OP_COMB (OP_ATTN + 8L*B_*S_)          // 4 slices of B*D
#define OP_GI0  (OP_COMB + 4L*B_*D_)          // 1 slice of B*3H each below
#define OP_GH0  (OP_GI0  + (long)B_*3*H_)
#define OP_GH1  (OP_GH0  + (long)B_*3*H_)
#define OP_GI1  (OP_GH1  + (long)B_*3*H_)
#define TOTP    (OP_GI1  + (long)B_*3*H_)

__device__ float g_part[TOTP];

// ---------------- split helpers ----------------
__device__ __forceinline__ void split2(float a, float b, unsigned& h, unsigned& l) {
    __nv_bfloat16 ha = __float2bfloat16(a), hb = __float2bfloat16(b);
    __nv_bfloat16 la = __float2bfloat16(a - __bfloat162float(ha));
    __nv_bfloat16 lb = __float2bfloat16(b - __bfloat162float(hb));
    h = ((unsigned)__bfloat16_as_ushort(hb) << 16) | (unsigned)__bfloat16_as_ushort(ha);
    l = ((unsigned)__bfloat16_as_ushort(lb) << 16) | (unsigned)__bfloat16_as_ushort(la);
}

__device__ __forceinline__ void split_store4(float4 a, __nv_bfloat16* hi,
                                             __nv_bfloat16* lo, long idx) {
    unsigned h01, h23, l01, l23;
    split2(a.x, a.y, h01, l01);
    split2(a.z, a.w, h23, l23);
    *reinterpret_cast<uint2*>(hi + idx) = make_uint2(h01, h23);
    *reinterpret_cast<uint2*>(lo + idx) = make_uint2(l01, l23);
}

__global__ void wconv(const float* __restrict__ s, __nv_bfloat16* __restrict__ hi,
                      __nv_bfloat16* __restrict__ lo, int n) {
    int i = blockIdx.x * 256 + threadIdx.x;
    if (i >= n) return;
    float v = s[i];
    __nv_bfloat16 h = __float2bfloat16(v);
    hi[i] = h;
    lo[i] = __float2bfloat16(v - __bfloat162float(h));
}

// ---------------- mma + ldmatrix + cp.async wrappers ------------------------
__device__ __forceinline__ void mma16816(float* c, const unsigned* a,
                                         unsigned b0, unsigned b1) {
    asm volatile(
        "mma.sync.aligned.m16n8k16.row.col.f32.bf16.bf16.f32 "
        "{%0,%1,%2,%3}, {%4,%5,%6,%7}, {%8,%9}, {%0,%1,%2,%3};\n"
        : "+f"(c[0]), "+f"(c[1]), "+f"(c[2]), "+f"(c[3])
        : "r"(a[0]), "r"(a[1]), "r"(a[2]), "r"(a[3]), "r"(b0), "r"(b1));
}

__device__ __forceinline__ void ldsm4(unsigned* f, unsigned addr) {
    asm volatile("ldmatrix.sync.aligned.m8n8.x4.shared.b16 {%0,%1,%2,%3}, [%4];"
                 : "=r"(f[0]), "=r"(f[1]), "=r"(f[2]), "=r"(f[3]) : "r"(addr));
}

__device__ __forceinline__ void cpa16(unsigned dst, const void* src) {
    asm volatile("cp.async.cg.shared.global [%0], [%1], 16;"
                 :: "r"(dst), "l"(src) : "memory");
}
__device__ __forceinline__ void cpa16z(unsigned dst, const void* src, int sz) {
    asm volatile("cp.async.cg.shared.global [%0], [%1], 16, %2;"
                 :: "r"(dst), "l"(src), "r"(sz) : "memory");
}

// =================== triple-problem split-K bf16 tensor GEMM ================
// C_part[zl][m][n] = sum_{k slice} (Ahi+Alo)[m,k] * (Whi+Wlo)[n,k]
// 3 products hi*hi + hi*lo + lo*hi, fp32 mma accumulate. A = virtual concat
// (k < K1 -> A1 else A2), all operands pre-split bf16. Store epilogue.
// 64x64 CTA tile, 128 threads (2x2 warps of 32x32), K-chunk 32, cp.async
// double buffer, ldmatrix fragment loads on 80B-stride (conflict-free) smem.
struct GemmSet {
    const __nv_bfloat16 *A1h, *A1l, *A2h, *A2l;
    const __nv_bfloat16 *Wh, *Wl;
    float* C;
    int K1, lda1, lda2, ldw, ldc, N, K, Kslice, zcount;
};

// array stride inside the smem tile: 64 rows * 20 u32 = 5120 BYTES
#define ARR_BYTES (64 * 20 * 4)

__global__ __launch_bounds__(128) void hgemm3(GemmSet s0, GemmSet s1, GemmSet s2) {
    // [buf][arr: Ah,Al,Wh,Wl][row 64][20 u32]  (16 data u32 + 4 pad)
    __shared__ unsigned sm[2 * 4 * 64 * 20];

    const int zg = blockIdx.z;
    GemmSet g; int zl;
    if (zg < s0.zcount)                     { g = s0; zl = zg; }
    else if (zg < s0.zcount + s1.zcount)    { g = s1; zl = zg - s0.zcount; }
    else                                    { g = s2; zl = zg - s0.zcount - s1.zcount; }
    const int n0 = blockIdx.x * 64, m0 = blockIdx.y * 64;
    if (n0 >= g.N) return;

    const int tid = threadIdx.x, warp = tid >> 5, lane = tid & 31;
    const int gq = lane >> 2, tq = lane & 3;
    const int wm0 = (warp & 1) * 32, wn0 = (warp >> 1) * 32;
    const int r = tid >> 1, half = tid & 1;
    const unsigned smb = (unsigned)__cvta_generic_to_shared(sm);

    // ldmatrix lane->address components (canonical m16n8k16 fragments)
    const int arow = (lane & 7) + ((lane >> 3) & 1) * 8;   // A mats: {+0,k},{+8,k},{+0,k+8},{+8,k+8}
    const int akof = ((lane >> 4) & 1) * 4;
    const int wrow = (lane & 7) + ((lane >> 4) & 1) * 8;   // W mats: {n,k},{n,k+8},{n+8,k},{n+8,k+8}
    const int wkof = ((lane >> 3) & 1) * 4;

    const int kstart = zl * g.Kslice;
    const int nch = g.Kslice >> 5;     // K-chunk = 32 bf16

    float acc[2][4][4];
#pragma unroll
    for (int mt = 0; mt < 2; mt++)
#pragma unroll
        for (int nt = 0; nt < 4; nt++)
#pragma unroll
            for (int q = 0; q < 4; q++) acc[mt][nt][q] = 0.f;

    const int nW = n0 + r;
    const int okW = (nW < g.N) ? 16 : 0;
    const long wbase = (long)((nW < g.N) ? nW : (g.N - 1)) * g.ldw + half * 16;

    auto loads = [&](int c) {
        const int buf = c & 1;
        const int kb = kstart + (c << 5);
        long abase;
        const __nv_bfloat16 *Ah, *Al;
        if (kb < g.K1) { Ah = g.A1h; Al = g.A1l; abase = (long)(m0 + r) * g.lda1 + kb + half * 16; }
        else           { Ah = g.A2h; Al = g.A2l; abase = (long)(m0 + r) * g.lda2 + (kb - g.K1) + half * 16; }
        unsigned d0 = smb + 4 * (((buf * 4 + 0) * 64 + r) * 20 + half * 8);
        unsigned d1 = smb + 4 * (((buf * 4 + 1) * 64 + r) * 20 + half * 8);
        unsigned d2 = smb + 4 * (((buf * 4 + 2) * 64 + r) * 20 + half * 8);
        unsigned d3 = smb + 4 * (((buf * 4 + 3) * 64 + r) * 20 + half * 8);
        cpa16(d0,      Ah + abase);     cpa16(d0 + 16, Ah + abase + 8);
        cpa16(d1,      Al + abase);     cpa16(d1 + 16, Al + abase + 8);
        cpa16z(d2,      g.Wh + wbase + kb,     okW);
        cpa16z(d2 + 16, g.Wh + wbase + kb + 8, okW);
        cpa16z(d3,      g.Wl + wbase + kb,     okW);
        cpa16z(d3 + 16, g.Wl + wbase + kb + 8, okW);
        asm volatile("cp.async.commit_group;" ::: "memory");
    };

    loads(0);
    for (int c = 0; c < nch; c++) {
        if (c + 1 < nch) {
            loads(c + 1);
            asm volatile("cp.async.wait_group 1;" ::: "memory");
        } else {
            asm volatile("cp.async.wait_group 0;" ::: "memory");
        }
        __syncthreads();                 // chunk c visible to all warps
        const int buf = c & 1;
#pragma unroll
        for (int kk = 0; kk < 2; kk++) {
            const int kw = kk * 8;
            unsigned ah[2][4], al[2][4], wh[2][4], wl[2][4];
#pragma unroll
            for (int mt = 0; mt < 2; mt++) {
                unsigned aaddr = smb + 4 * (((buf * 4 + 0) * 64 + wm0 + mt * 16 + arow) * 20 + kw + akof);
                ldsm4(ah[mt], aaddr);
                ldsm4(al[mt], aaddr + ARR_BYTES);         // Al = Ah + one array
            }
#pragma unroll
            for (int p = 0; p < 2; p++) {
                unsigned waddr = smb + 4 * (((buf * 4 + 2) * 64 + wn0 + p * 16 + wrow) * 20 + kw + wkof);
                ldsm4(wh[p], waddr);
                ldsm4(wl[p], waddr + ARR_BYTES);          // Wl = Wh + one array
            }
#pragma unroll
            for (int mt = 0; mt < 2; mt++)
#pragma unroll
                for (int p = 0; p < 2; p++) {
                    mma16816(acc[mt][2 * p],     ah[mt], wh[p][0], wh[p][1]);
                    mma16816(acc[mt][2 * p],     ah[mt], wl[p][0], wl[p][1]);
                    mma16816(acc[mt][2 * p],     al[mt], wh[p][0], wh[p][1]);
                    mma16816(acc[mt][2 * p + 1], ah[mt], wh[p][2], wh[p][3]);
                    mma16816(acc[mt][2 * p + 1], ah[mt], wl[p][2], wl[p][3]);
                    mma16816(acc[mt][2 * p + 1], al[mt], wh[p][2], wh[p][3]);
                }
        }
        __syncthreads();                 // done reading buf before it is refilled
    }

    float* Cs = g.C + (long)zl * ((long)256 * g.ldc);
#pragma unroll
    for (int mt = 0; mt < 2; mt++) {
        int m = m0 + wm0 + mt * 16 + gq;
#pragma unroll
        for (int nt = 0; nt < 4; nt++) {
            int n = n0 + wn0 + nt * 8 + 2 * tq;
            if (n < g.N) {
                *reinterpret_cast<float2*>(Cs + (long)m * g.ldc + n) =
                    make_float2(acc[mt][nt][0], acc[mt][nt][1]);
                *reinterpret_cast<float2*>(Cs + (long)(m + 8) * g.ldc + n) =
                    make_float2(acc[mt][nt][2], acc[mt][nt][3]);
            }
        }
    }
}

// ---------------- fused logits-reduce + softmax + weighted enc --------------
__global__ void softmax_wenc(const float* __restrict__ lp,
                             const float* __restrict__ bias,
                             float* __restrict__ outAttn, int t,
                             const float* __restrict__ enc,
                             __nv_bfloat16* __restrict__ whi,
                             __nv_bfloat16* __restrict__ wlo) {
    __shared__ float sw[S_];
    const int b = blockIdx.y, c = blockIdx.x, lane = threadIdx.x;
    float v[3];
#pragma unroll
    for (int j = 0; j < 3; j++) {
        int s = lane + 32 * j;
        float a = bias[s];
#pragma unroll
        for (int z = 0; z < 8; z++) a += lp[(long)z * (B_ * S_) + b * S_ + s];
        v[j] = a;
    }
    float mx = fmaxf(v[0], fmaxf(v[1], v[2]));
#pragma unroll
    for (int o = 16; o; o >>= 1) mx = fmaxf(mx, __shfl_xor_sync(0xffffffffu, mx, o));
    float e[3], sum = 0.f;
#pragma unroll
    for (int j = 0; j < 3; j++) { e[j] = expf(v[j] - mx); sum += e[j]; }
#pragma unroll
    for (int o = 16; o; o >>= 1) sum += __shfl_xor_sync(0xffffffffu, sum, o);
    const float inv = 1.f / sum;
#pragma unroll
    for (int j = 0; j < 3; j++) sw[lane + 32 * j] = e[j] * inv;
    __syncwarp();
    if (c == 0) {
#pragma unroll
        for (int j = 0; j < 3; j++)
            outAttn[((long)b * T_ + t) * S_ + lane + 32 * j] = sw[lane + 32 * j];
    }
    const float4* ep = reinterpret_cast<const float4*>(enc + (long)b * S_ * H_) + c * 32 + lane;
    float4 acc = make_float4(0.f, 0.f, 0.f, 0.f);
#pragma unroll 4
    for (int s = 0; s < S_; s++) {
        float w = sw[s];
        float4 x = ep[(long)s * (H_ / 4)];
        acc.x = fmaf(w, x.x, acc.x);
        acc.y = fmaf(w, x.y, acc.y);
        acc.z = fmaf(w, x.z, acc.z);
        acc.w = fmaf(w, x.w, acc.w);
    }
    split_store4(acc, whi, wlo, (long)b * H_ + c * 128 + lane * 4);
}

// ------- reduce nsum split-K partials (cols=1024) + bias (+relu) + split ----
__global__ void reduce_split(const float* __restrict__ P,
                             const float* __restrict__ bias, int relu, int nsum,
                             long sstride4,
                             __nv_bfloat16* __restrict__ hi,
                             __nv_bfloat16* __restrict__ lo, long total4) {
    long i4 = (long)blockIdx.x * 256 + threadIdx.x;
    if (i4 >= total4) return;
    int d4 = (int)(i4 & 255);
    float4 a = reinterpret_cast<const float4*>(bias)[d4];
    for (int z = 0; z < nsum; z++) {
        float4 p = reinterpret_cast<const float4*>(P)[z * sstride4 + i4];
        a.x += p.x; a.y += p.y; a.z += p.z; a.w += p.w;
    }
    if (relu) {
        a.x = fmaxf(a.x, 0.f); a.y = fmaxf(a.y, 0.f);
        a.z = fmaxf(a.z, 0.f); a.w = fmaxf(a.w, 0.f);
    }
    split_store4(a, hi, lo, i4 * 4);
}

// ---------------- GRU gate: single-slice gi/gh, h = (1-z)*n + z*h -----------
__global__ void gru_gate(const float* __restrict__ gi, const float* __restrict__ gh,
                         const float* __restrict__ bi, const float* __restrict__ bh,
                         float* __restrict__ h,
                         __nv_bfloat16* __restrict__ hhi, __nv_bfloat16* __restrict__ hlo,
                         __nv_bfloat16* __restrict__ histh, __nv_bfloat16* __restrict__ histl) {
    int i4 = blockIdx.x * 256 + threadIdx.x;            // over B*H/4
    int b = i4 >> 8, j4 = i4 & 255;
    const long row4 = (long)b * (3 * H_ / 4);
    const float4* bi4 = reinterpret_cast<const float4*>(bi);
    const float4* bh4 = reinterpret_cast<const float4*>(bh);
    const float4* gi4 = reinterpret_cast<const float4*>(gi) + row4;
    const float4* gh4 = reinterpret_cast<const float4*>(gh) + row4;

    float4 ir = bi4[j4], iz = bi4[j4 + 256], in_ = bi4[j4 + 512];
    float4 hr = bh4[j4], hz = bh4[j4 + 256], hn = bh4[j4 + 512];
    float4 p;
    p = gi4[j4];       ir.x += p.x; ir.y += p.y; ir.z += p.z; ir.w += p.w;
    p = gi4[j4 + 256]; iz.x += p.x; iz.y += p.y; iz.z += p.z; iz.w += p.w;
    p = gi4[j4 + 512]; in_.x += p.x; in_.y += p.y; in_.z += p.z; in_.w += p.w;
    p = gh4[j4];       hr.x += p.x; hr.y += p.y; hr.z += p.z; hr.w += p.w;
    p = gh4[j4 + 256]; hz.x += p.x; hz.y += p.y; hz.z += p.z; hz.w += p.w;
    p = gh4[j4 + 512]; hn.x += p.x; hn.y += p.y; hn.z += p.z; hn.w += p.w;

    float4 hv = reinterpret_cast<float4*>(h)[i4];
    float rr[4] = {ir.x + hr.x, ir.y + hr.y, ir.z + hr.z, ir.w + hr.w};
    float zz[4] = {iz.x + hz.x, iz.y + hz.y, iz.z + hz.z, iz.w + hz.w};
    float nn[4] = {in_.x, in_.y, in_.z, in_.w};
    float hnv[4] = {hn.x, hn.y, hn.z, hn.w};
    float ho[4] = {hv.x, hv.y, hv.z, hv.w};
    float res[4];
#pragma unroll
    for (int q = 0; q < 4; q++) {
        float r = 1.f / (1.f + expf(-rr[q]));
        float z = 1.f / (1.f + expf(-zz[q]));
        float n = tanhf(nn[q] + r * hnv[q]);
        res[q] = (1.f - z) * n + z * ho[q];
    }
    float4 out = make_float4(res[0], res[1], res[2], res[3]);
    reinterpret_cast<float4*>(h)[i4] = out;
    split_store4(out, hhi, hlo, (long)i4 * 4);
    if (histh) split_store4(out, histh, histl, (long)i4 * 4);
}

// ---------------- tail: y writeback with (t*B+b) -> (b,t) remap -------------
__global__ void copy_y_all(const float* __restrict__ Y, const float* __restrict__ b2,
                           float* __restrict__ outy) {
    long i4 = (long)blockIdx.x * 256 + threadIdx.x;     // over B*T*D/4
    long row = i4 >> 8;                                 // t*B + b
    int d4 = (int)(i4 & 255);
    int t = (int)(row / B_), b = (int)(row % B_);
    float4 a = reinterpret_cast<const float4*>(b2)[d4];
    float4 p = reinterpret_cast<const float4*>(Y)[i4];
    a.x += p.x; a.y += p.y; a.z += p.z; a.w += p.w;
    reinterpret_cast<float4*>(outy)[((long)b * T_ + t) * 256 + d4] = a;
}

// ---------------- host driver ----------------
static inline GemmSet mkset(const __nv_bfloat16* A1h, const __nv_bfloat16* A1l,
                            const __nv_bfloat16* A2h, const __nv_bfloat16* A2l,
                            int K1, int lda1, int lda2,
                            const __nv_bfloat16* Wh, const __nv_bfloat16* Wl, int ldw,
                            float* C, int ldc, int N, int K, int Kslice, int zc) {
    GemmSet s;
    s.A1h = A1h; s.A1l = A1l; s.A2h = A2h; s.A2l = A2l;
    s.Wh = Wh; s.Wl = Wl; s.C = C;
    s.K1 = K1; s.lda1 = lda1; s.lda2 = lda2; s.ldw = ldw; s.ldc = ldc;
    s.N = N; s.K = K; s.Kslice = Kslice; s.zcount = zc;
    return s;
}

extern "C" void kernel_launch(void* const* d_in, const int* in_sizes, int n_in,
                              void* d_out, int out_size) {
    const float* target = (const float*)d_in[0];   // (B,T,D)
    const float* hidden0= (const float*)d_in[1];   // (L,B,H)
    const float* enc    = (const float*)d_in[2];   // (B,S,H)
    const float* attn_W = (const float*)d_in[3];
    const float* attn_b = (const float*)d_in[4];
    const float* comb_W = (const float*)d_in[5];
    const float* comb_b = (const float*)d_in[6];
    const float* W_ih   = (const float*)d_in[7];
    const float* W_hh   = (const float*)d_in[8];
    const float* b_ih   = (const float*)d_in[9];
    const float* b_hh   = (const float*)d_in[10];
    const float* out1_W = (const float*)d_in[11];
    const float* out1_b = (const float*)d_in[12];
    const float* out2_W = (const float*)d_in[13];
    const float* out2_b = (const float*)d_in[14];

    float* out     = (float*)d_out;
    float* outY    = out;
    float* hid     = out + Y_SZ;
    float* outAttn = out + Y_SZ + HID_SZ;

    __nv_bfloat16 *whi, *wlo, *bhi, *blo, *histh, *histl, *t1h, *t1l;
    float *part, *big;
    cudaGetSymbolAddress((void**)&whi, g_whi);
    cudaGetSymbolAddress((void**)&wlo, g_wlo);
    cudaGetSymbolAddress((void**)&bhi, g_bhi);
    cudaGetSymbolAddress((void**)&blo, g_blo);
    cudaGetSymbolAddress((void**)&histh, g_histh);
    cudaGetSymbolAddress((void**)&histl, g_histl);
    cudaGetSymbolAddress((void**)&t1h, g_t1h);
    cudaGetSymbolAddress((void**)&t1l, g_t1l);
    cudaGetSymbolAddress((void**)&part, g_part);
    cudaGetSymbolAddress((void**)&big, g_big);

    float* h0 = hid;
    float* h1 = hid + (long)B_ * H_;
    __nv_bfloat16 *h0hi = bhi + OB_H, *h0lo = blo + OB_H;
    __nv_bfloat16 *h1hi = bhi + OB_H + (long)B_ * H_, *h1lo = blo + OB_H + (long)B_ * H_;

    // ---- per-replay weight + target + initial hidden splits ----
    {
        struct { const float* s; long off; long n; } cv[6] = {
            {attn_W, OW_ATTN, NW_ATTN}, {comb_W, OW_COMB, NW_COMB},
            {W_ih,   OW_IH,   NW_IH},   {W_hh,   OW_HH,   NW_HH},
            {out1_W, OW_O1,   NW_O1},   {out2_W, OW_O2,   NW_O2}};
        for (int i = 0; i < 6; i++)
            wconv<<<(int)((cv[i].n + 255) / 256), 256>>>(cv[i].s, whi + cv[i].off,
                                                         wlo + cv[i].off, (int)cv[i].n);
    }
    wconv<<<(int)((Y_SZ + 255) / 256), 256>>>(target, bhi + OB_X, blo + OB_X, (int)Y_SZ);
    cudaMemcpyAsync(hid, hidden0, HID_SZ * sizeof(float), cudaMemcpyDeviceToDevice, 0);
    wconv<<<(int)((HID_SZ + 255) / 256), 256>>>(hid, bhi + OB_H, blo + OB_H, (int)HID_SZ);

    auto xh = [&](int t) { return bhi + OB_X + (long)t * D_; };
    auto xl = [&](int t) { return blo + OB_X + (long)t * D_; };

    GemmSet dummy = {};
    dummy.zcount = 0;

    auto launchM = [&](const GemmSet& s, int mtiles) {
        dim3 grd((s.N + 63) / 64, mtiles, s.zcount);
        hgemm3<<<grd, 128>>>(s, dummy, dummy);
    };
    auto launch3 = [&](const GemmSet& a, const GemmSet& b, const GemmSet& c) {
        dim3 grd((a.N + 63) / 64, B_ / 64, a.zcount + b.zcount + c.zcount);
        hgemm3<<<grd, 128>>>(a, b, c);
    };

    for (int t = 0; t < T_; t++) {
        // attention logits: [x|h1] @ attn_W^T, split-K z=8
        launchM(mkset(xh(t), xl(t), h1hi, h1lo, D_, T_ * D_, H_,
                      whi + OW_ATTN, wlo + OW_ATTN, D_ + H_,
                      part + OP_ATTN, S_, S_, D_ + H_, 256, 8), B_ / 64);
        softmax_wenc<<<dim3(8, B_), 32>>>(part + OP_ATTN, attn_b, outAttn, t, enc,
                                          bhi + OB_WE, blo + OB_WE);
        // combine: [x|wenc] @ comb_W^T, z=4
        launchM(mkset(xh(t), xl(t), bhi + OB_WE, blo + OB_WE, D_, T_ * D_, H_,
                      whi + OW_COMB, wlo + OW_COMB, D_ + H_,
                      part + OP_COMB, D_, D_, D_ + H_, 512, 4), B_ / 64);
        reduce_split<<<256, 256>>>(part + OP_COMB, comb_b, 1, 4, (long)B_ * D_ / 4,
                                   bhi + OB_XC, blo + OB_XC, (long)B_ * D_ / 4);
        // GRU: gi0 + gh0 + gh1 (gh1 reads old h1) in one launch, z=1 each
        launch3(
            mkset(bhi + OB_XC, blo + OB_XC, bhi + OB_XC, blo + OB_XC, D_, D_, D_,
                  whi + OW_IH, wlo + OW_IH, D_, part + OP_GI0, 3 * H_, 3 * H_, D_, D_, 1),
            mkset(h0hi, h0lo, h0hi, h0lo, H_, H_, H_,
                  whi + OW_HH, wlo + OW_HH, H_, part + OP_GH0, 3 * H_, 3 * H_, H_, H_, 1),
            mkset(h1hi, h1lo, h1hi, h1lo, H_, H_, H_,
                  whi + OW_HH + 3L * H_ * H_, wlo + OW_HH + 3L * H_ * H_, H_,
                  part + OP_GH1, 3 * H_, 3 * H_, H_, H_, 1));
        gru_gate<<<256, 256>>>(part + OP_GI0, part + OP_GH0, b_ih, b_hh,
                               h0, h0hi, h0lo, nullptr, nullptr);
        launchM(mkset(h0hi, h0lo, h0hi, h0lo, H_, H_, H_,
                      whi + OW_IH + 3L * H_ * D_, wlo + OW_IH + 3L * H_ * D_, D_,
                      part + OP_GI1, 3 * H_, 3 * H_, D_, D_, 1), B_ / 64);
        gru_gate<<<256, 256>>>(part + OP_GI1, part + OP_GH1,
                               b_ih + 3 * H_, b_hh + 3 * H_,
                               h1, h1hi, h1lo,
                               histh + (long)t * B_ * H_, histl + (long)t * B_ * H_);
    }

    // ---- deferred output head: two M = B*T GEMMs ----
    const int MT = (B_ * T_) / 64;   // 144 m-tiles
    launchM(mkset(histh, histl, histh, histl, H_, H_, H_,
                  whi + OW_O1, wlo + OW_O1, H_, big, D_, D_, H_, H_, 1), MT);
    reduce_split<<<(int)((NBT / 4 + 255) / 256), 256>>>(big, out1_b, 0, 1, 0,
                                                        t1h, t1l, NBT / 4);
    launchM(mkset(t1h, t1l, t1h, t1l, D_, D_, D_,
                  whi + OW_O2, wlo + OW_O2, D_, big, D_, D_, D_, D_, 1), MT);
    copy_y_all<<<(int)((NBT / 4 + 255) / 256), 256>>>(big, out2_b, outY);
}